// round 10
// baseline (speedup 1.0000x reference)
#include <cuda_runtime.h>
#include <math.h>

// Problem constants (fixed by dataset)
#define NPAD   3000
#define H1DIM  256
#define OUTD   128
#define NGATE  4
#define EMAX   300000
#define FIN    1024
#define SPLITK 4

// ---------------- scratch (static; no allocation allowed) ----------------
__device__ float d_xh[NPAD * H1DIM];                 // relu(x@W0^T+b) [3000,256]
__device__ float d_xh_part[SPLITK * NPAD * H1DIM];   // split-K partials
__device__ float d_agg[NPAD * H1DIM];                // segment mean   [3000,256]
__device__ float d_g[NPAD * NGATE * OUTD];           // gates          [3000,512]
__device__ int   d_deg[NPAD];
__device__ int   d_rowptr[NPAD + 1];
__device__ int   d_cursor[NPAD];
__device__ int   d_csr[EMAX];

// ---------------- f32x2 packed-FMA helpers (Blackwell FFMA2) ----------------
typedef unsigned long long u64;

__device__ __forceinline__ void ffma2(u64& d, u64 a, u64 b) {
    asm("fma.rn.f32x2 %0, %1, %2, %3;" : "=l"(d) : "l"(a), "l"(b), "l"(d));
}
__device__ __forceinline__ u64 pack2(float lo, float hi) {
    u64 r; asm("mov.b64 %0, {%1, %2};" : "=l"(r) : "f"(lo), "f"(hi)); return r;
}
__device__ __forceinline__ float2 unpack2(u64 v) {
    float2 r; asm("mov.b64 {%0, %1}, %2;" : "=f"(r.x), "=f"(r.y) : "l"(v)); return r;
}
__device__ __forceinline__ float sigmoidf_(float x) {
    return 1.0f / (1.0f + __expf(-x));
}

// ---------------- CSR build ----------------
__global__ void init_kernel() {
    int i = blockIdx.x * blockDim.x + threadIdx.x;
    if (i < NPAD) { d_deg[i] = 0; d_cursor[i] = 0; }
}

__global__ void hist_kernel(const int* __restrict__ ei, int E) {
    int e = blockIdx.x * blockDim.x + threadIdx.x;
    if (e < E) atomicAdd(&d_deg[ei[E + e]], 1);   // row 1 = dst
}

// single-block exclusive scan over 3000 degrees -> rowptr (+ total at [3000])
__global__ void scan_kernel() {
    __shared__ int wsum[32];
    int t = threadIdx.x;                 // 1024 threads
    int base = t * 3;
    int v0 = (base     < NPAD) ? d_deg[base]     : 0;
    int v1 = (base + 1 < NPAD) ? d_deg[base + 1] : 0;
    int v2 = (base + 2 < NPAD) ? d_deg[base + 2] : 0;
    int s = v0 + v1 + v2;
    int lane = t & 31, wid = t >> 5;
    int x = s;
    #pragma unroll
    for (int o = 1; o < 32; o <<= 1) {
        int y = __shfl_up_sync(0xFFFFFFFFu, x, o);
        if (lane >= o) x += y;
    }
    if (lane == 31) wsum[wid] = x;
    __syncthreads();
    if (wid == 0) {
        int y = wsum[lane];
        #pragma unroll
        for (int o = 1; o < 32; o <<= 1) {
            int z = __shfl_up_sync(0xFFFFFFFFu, y, o);
            if (lane >= o) y += z;
        }
        wsum[lane] = y;
    }
    __syncthreads();
    int incl = x + (wid > 0 ? wsum[wid - 1] : 0);
    int excl = incl - s;
    if (base     < NPAD) d_rowptr[base]     = excl;
    if (base + 1 < NPAD) d_rowptr[base + 1] = excl + v0;
    if (base + 2 < NPAD) d_rowptr[base + 2] = excl + v0 + v1;
    if (t == 1023) d_rowptr[NPAD] = incl;
}

__global__ void scatter_kernel(const int* __restrict__ ei, int E) {
    int e = blockIdx.x * blockDim.x + threadIdx.x;
    if (e < E) {
        int dst = ei[E + e];
        int pos = atomicAdd(&d_cursor[dst], 1);
        d_csr[d_rowptr[dst] + pos] = ei[e];   // src
    }
}

// ---- GEMM tile geometry: 64x64x16, 128 threads, 4x8/thread, double-buffer --
#define BM 64
#define BN 64
#define BK 16

// GEMM1 (split-K): part[z] = x[:, zK:(z+1)K] @ fc0_w[:, zK:(z+1)K]^T
// A [M,1024] K-contig, B [256,1024] K-contig (NT).
__global__ __launch_bounds__(128)
void gemm1_kernel(const float* __restrict__ A, const float* __restrict__ B, int M) {
    __shared__ float As[2][BK][BM];
    __shared__ float Bs[2][BK][BN];
    int tid = threadIdx.x;
    int m0 = blockIdx.x * BM;
    int n0 = blockIdx.y * BN;
    int kbase = blockIdx.z * (FIN / SPLITK);
    float* part = d_xh_part + blockIdx.z * (NPAD * H1DIM);

    int tx = tid & 7;          // 8 col-groups of 8
    int ty = tid >> 3;         // 16 row-groups of 4
    int lmq = tid >> 2;        // 0..31
    int lk4 = (tid & 3) * 4;   // k offset 0,4,8,12

    u64 acc[4][4];
    #pragma unroll
    for (int i = 0; i < 4; ++i)
        #pragma unroll
        for (int j = 0; j < 4; ++j) acc[i][j] = 0ull;

    const int NT = (FIN / SPLITK) / BK;   // 16 tiles
    float4 va[2], vb[2];

    // prologue: fetch tile 0
    #pragma unroll
    for (int p = 0; p < 2; ++p) {
        int m = p * 32 + lmq;
        va[p] = make_float4(0.f, 0.f, 0.f, 0.f);
        if (m0 + m < M)
            va[p] = *(const float4*)&A[(m0 + m) * FIN + kbase + lk4];
        vb[p] = *(const float4*)&B[(n0 + m) * FIN + kbase + lk4];
    }
    #pragma unroll
    for (int p = 0; p < 2; ++p) {
        int m = p * 32 + lmq;
        As[0][lk4 + 0][m] = va[p].x; As[0][lk4 + 1][m] = va[p].y;
        As[0][lk4 + 2][m] = va[p].z; As[0][lk4 + 3][m] = va[p].w;
        Bs[0][lk4 + 0][m] = vb[p].x; Bs[0][lk4 + 1][m] = vb[p].y;
        Bs[0][lk4 + 2][m] = vb[p].z; Bs[0][lk4 + 3][m] = vb[p].w;
    }
    __syncthreads();

    for (int t = 0; t < NT; ++t) {
        int cur = t & 1, nxt = cur ^ 1;
        if (t + 1 < NT) {
            int k0 = (t + 1) * BK;
            #pragma unroll
            for (int p = 0; p < 2; ++p) {
                int m = p * 32 + lmq;
                va[p] = make_float4(0.f, 0.f, 0.f, 0.f);
                if (m0 + m < M)
                    va[p] = *(const float4*)&A[(m0 + m) * FIN + kbase + k0 + lk4];
                vb[p] = *(const float4*)&B[(n0 + m) * FIN + kbase + k0 + lk4];
            }
        }
        #pragma unroll
        for (int k = 0; k < BK; ++k) {
            float4 a  = *(const float4*)&As[cur][k][ty * 4];
            float4 b0 = *(const float4*)&Bs[cur][k][tx * 8];
            float4 b1 = *(const float4*)&Bs[cur][k][tx * 8 + 4];
            u64 bp[4] = { pack2(b0.x, b0.y), pack2(b0.z, b0.w),
                          pack2(b1.x, b1.y), pack2(b1.z, b1.w) };
            float av[4] = { a.x, a.y, a.z, a.w };
            #pragma unroll
            for (int i = 0; i < 4; ++i) {
                u64 ad = pack2(av[i], av[i]);
                #pragma unroll
                for (int j = 0; j < 4; ++j) ffma2(acc[i][j], ad, bp[j]);
            }
        }
        if (t + 1 < NT) {
            #pragma unroll
            for (int p = 0; p < 2; ++p) {
                int m = p * 32 + lmq;
                As[nxt][lk4 + 0][m] = va[p].x; As[nxt][lk4 + 1][m] = va[p].y;
                As[nxt][lk4 + 2][m] = va[p].z; As[nxt][lk4 + 3][m] = va[p].w;
                Bs[nxt][lk4 + 0][m] = vb[p].x; Bs[nxt][lk4 + 1][m] = vb[p].y;
                Bs[nxt][lk4 + 2][m] = vb[p].z; Bs[nxt][lk4 + 3][m] = vb[p].w;
            }
        }
        __syncthreads();
    }

    #pragma unroll
    for (int i = 0; i < 4; ++i) {
        int m = m0 + ty * 4 + i;
        if (m >= M) continue;
        #pragma unroll
        for (int j = 0; j < 4; ++j) {
            float2 v = unpack2(acc[i][j]);
            *(float2*)&part[m * H1DIM + n0 + tx * 8 + j * 2] = v;
        }
    }
}

// xh = relu(sum_z part[z] + bias) for real rows
__global__ __launch_bounds__(256)
void xh_epilogue_kernel(const float* __restrict__ bias, int n_real) {
    int idx = blockIdx.x * blockDim.x + threadIdx.x;   // float4 index
    int total = n_real * (H1DIM / 4);
    if (idx >= total) return;
    int c4 = idx & 63;
    const float4* p0 = (const float4*)(d_xh_part);
    const float4* p1 = (const float4*)(d_xh_part + 1 * NPAD * H1DIM);
    const float4* p2 = (const float4*)(d_xh_part + 2 * NPAD * H1DIM);
    const float4* p3 = (const float4*)(d_xh_part + 3 * NPAD * H1DIM);
    float4 a = p0[idx], b = p1[idx], c = p2[idx], d = p3[idx];
    float4 bs = ((const float4*)bias)[c4];
    float4 r;
    r.x = fmaxf(a.x + b.x + c.x + d.x + bs.x, 0.f);
    r.y = fmaxf(a.y + b.y + c.y + d.y + bs.y, 0.f);
    r.z = fmaxf(a.z + b.z + c.z + d.z + bs.z, 0.f);
    r.w = fmaxf(a.w + b.w + c.w + d.w + bs.w, 0.f);
    ((float4*)d_xh)[idx] = r;
}

// padded rows [n_real,3000): xh = relu(fc0_b)
__global__ void fill_xh_kernel(const float* __restrict__ bias, int n_real) {
    int r = n_real + blockIdx.x;
    d_xh[r * H1DIM + threadIdx.x] = fmaxf(bias[threadIdx.x], 0.f);
}

// ---------------- aggregation: agg[n] = mean_{dst==n} xh[src] ----------------
// 2 nodes per 128-thread CTA; 8-deep gather batches for MLP.
__global__ __launch_bounds__(128)
void agg_kernel() {
    int n   = blockIdx.x * 2 + (threadIdx.x >> 6);
    int tid = threadIdx.x & 63;
    if (n >= NPAD) return;
    int beg = d_rowptr[n], end = d_rowptr[n + 1];
    const float4* xh4 = (const float4*)d_xh;
    float4 acc = make_float4(0.f, 0.f, 0.f, 0.f);
    int i = beg;
    for (; i + 8 <= end; i += 8) {
        int s[8];
        #pragma unroll
        for (int q = 0; q < 8; ++q) s[q] = d_csr[i + q];
        float4 v[8];
        #pragma unroll
        for (int q = 0; q < 8; ++q) v[q] = xh4[s[q] * 64 + tid];
        #pragma unroll
        for (int q = 0; q < 8; ++q) {
            acc.x += v[q].x; acc.y += v[q].y;
            acc.z += v[q].z; acc.w += v[q].w;
        }
    }
    for (; i < end; ++i) {
        float4 a = xh4[d_csr[i] * 64 + tid];
        acc.x += a.x; acc.y += a.y; acc.z += a.z; acc.w += a.w;
    }
    float inv = 1.0f / (float)max(end - beg, 1);
    acc.x *= inv; acc.y *= inv; acc.z *= inv; acc.w *= inv;
    ((float4*)d_agg)[n * 64 + tid] = acc;
}

// ---------------- GEMM2 (dual): g = agg@Wx_rel + xh@Wx_root + (bx+bh) -------
// A [3000,256] K-contig; B [4,256,128] N-contig per gate (NN).
// 32 logical tiles: t in [0,16) -> (agg, Wx_rel), t in [16,32) -> (xh, Wx_root)
__global__ __launch_bounds__(128)
void gemm2_kernel(const float* __restrict__ Brel, const float* __restrict__ Broot,
                  const float* __restrict__ bx, const float* __restrict__ bh) {
    __shared__ float As[2][BK][BM];
    __shared__ float Bs[2][BK][BN];
    int tid = threadIdx.x;
    int m0 = blockIdx.x * BM;
    int nG = blockIdx.y * BN;     // global gate-column [0,512)
    int gate = nG >> 7;
    int off  = nG & 127;
    const float* Ap[2] = { d_agg, d_xh };
    const float* Bp[2] = { Brel  + gate * H1DIM * OUTD + off,
                           Broot + gate * H1DIM * OUTD + off };
    int tx = tid & 7;
    int ty = tid >> 3;
    int lmq = tid >> 2;
    int lk4 = (tid & 3) * 4;
    int bk  = tid >> 4;           // 0..7 (B k-row per pass)
    int bn4 = (tid & 15) * 4;     // B col*4

    u64 acc[4][4];
    #pragma unroll
    for (int i = 0; i < 4; ++i)
        #pragma unroll
        for (int j = 0; j < 4; ++j) acc[i][j] = 0ull;

    const int NTP = H1DIM / BK;   // 16 tiles per phase
    const int NT  = 2 * NTP;      // 32 total
    float4 va[2], vb[2];

    // prologue: fetch tile 0 (phase 0, k0 = 0)
    {
        const float* A = Ap[0];
        const float* B = Bp[0];
        #pragma unroll
        for (int p = 0; p < 2; ++p) {
            int m = p * 32 + lmq;
            va[p] = make_float4(0.f, 0.f, 0.f, 0.f);
            if (m0 + m < NPAD)
                va[p] = *(const float4*)&A[(m0 + m) * H1DIM + lk4];
            int kk = bk + p * 8;
            vb[p] = *(const float4*)&B[kk * OUTD + bn4];
        }
        #pragma unroll
        for (int p = 0; p < 2; ++p) {
            int m = p * 32 + lmq;
            As[0][lk4 + 0][m] = va[p].x; As[0][lk4 + 1][m] = va[p].y;
            As[0][lk4 + 2][m] = va[p].z; As[0][lk4 + 3][m] = va[p].w;
            int kk = bk + p * 8;
            *(float4*)&Bs[0][kk][bn4] = vb[p];
        }
    }
    __syncthreads();

    for (int t = 0; t < NT; ++t) {
        int cur = t & 1, nxt = cur ^ 1;
        if (t + 1 < NT) {
            int tn = t + 1;
            const float* A = Ap[tn >> 4];
            const float* B = Bp[tn >> 4];
            int k0 = (tn & 15) * BK;
            #pragma unroll
            for (int p = 0; p < 2; ++p) {
                int m = p * 32 + lmq;
                va[p] = make_float4(0.f, 0.f, 0.f, 0.f);
                if (m0 + m < NPAD)
                    va[p] = *(const float4*)&A[(m0 + m) * H1DIM + k0 + lk4];
                int kk = bk + p * 8;
                vb[p] = *(const float4*)&B[(k0 + kk) * OUTD + bn4];
            }
        }
        #pragma unroll
        for (int k = 0; k < BK; ++k) {
            float4 a  = *(const float4*)&As[cur][k][ty * 4];
            float4 b0 = *(const float4*)&Bs[cur][k][tx * 8];
            float4 b1 = *(const float4*)&Bs[cur][k][tx * 8 + 4];
            u64 bp[4] = { pack2(b0.x, b0.y), pack2(b0.z, b0.w),
                          pack2(b1.x, b1.y), pack2(b1.z, b1.w) };
            float av[4] = { a.x, a.y, a.z, a.w };
            #pragma unroll
            for (int i = 0; i < 4; ++i) {
                u64 ad = pack2(av[i], av[i]);
                #pragma unroll
                for (int j = 0; j < 4; ++j) ffma2(acc[i][j], ad, bp[j]);
            }
        }
        if (t + 1 < NT) {
            #pragma unroll
            for (int p = 0; p < 2; ++p) {
                int m = p * 32 + lmq;
                As[nxt][lk4 + 0][m] = va[p].x; As[nxt][lk4 + 1][m] = va[p].y;
                As[nxt][lk4 + 2][m] = va[p].z; As[nxt][lk4 + 3][m] = va[p].w;
                int kk = bk + p * 8;
                *(float4*)&Bs[nxt][kk][bn4] = vb[p];
            }
        }
        __syncthreads();
    }

    // epilogue: bias sums hoisted (reused across all 4 m-rows)
    float2 bsum[4];
    #pragma unroll
    for (int j = 0; j < 4; ++j) {
        int cl = off + tx * 8 + j * 2;
        bsum[j].x = bx[gate * OUTD + cl]     + bh[gate * OUTD + cl];
        bsum[j].y = bx[gate * OUTD + cl + 1] + bh[gate * OUTD + cl + 1];
    }
    #pragma unroll
    for (int i = 0; i < 4; ++i) {
        int m = m0 + ty * 4 + i;
        if (m >= NPAD) continue;
        #pragma unroll
        for (int j = 0; j < 4; ++j) {
            float2 v = unpack2(acc[i][j]);
            v.x += bsum[j].x;
            v.y += bsum[j].y;
            *(float2*)&d_g[m * (NGATE * OUTD) + nG + tx * 8 + j * 2] = v;
        }
    }
}

// ---------------- LSTM gates + linear head ---------------------------------
// C0 = 0 -> C = sigmoid(g0)*tanh(g2); H = sigmoid(g3)*tanh(C)
// 2 nodes per 256-thread CTA: tid>>7 selects node, tid&127 the feature.
__global__ __launch_bounds__(256)
void lstm_out_kernel(const float* __restrict__ fc_w, const float* __restrict__ fc_b,
                     float* __restrict__ out, int n_real, int write_H,
                     float* __restrict__ Hout) {
    __shared__ float ws[2][4];
    int half = threadIdx.x >> 7;          // 0 or 1
    int n = blockIdx.x * 2 + half;
    int o = threadIdx.x & 127;
    if (n >= NPAD) return;
    const float* g = &d_g[n * (NGATE * OUTD)];
    float I = sigmoidf_(g[o]);
    float T = tanhf(g[2 * OUTD + o]);
    float O = sigmoidf_(g[3 * OUTD + o]);
    float C = I * T;
    float h = O * tanhf(C);
    if (write_H) Hout[n * OUTD + o] = h;
    float v = h * fc_w[o];
    #pragma unroll
    for (int off = 16; off; off >>= 1)
        v += __shfl_down_sync(0xFFFFFFFFu, v, off);
    if ((o & 31) == 0) ws[half][o >> 5] = v;
    __syncthreads();
    if (o == 0 && n < n_real)
        out[n] = ws[half][0] + ws[half][1] + ws[half][2] + ws[half][3] + fc_b[0];
}

// ---------------- launch ---------------------------------------------------
extern "C" void kernel_launch(void* const* d_in, const int* in_sizes, int n_in,
                              void* d_out, int out_size) {
    const float* x      = (const float*)d_in[0];
    const int*   ei     = (const int*)  d_in[1];
    const float* fc0_w  = (const float*)d_in[2];
    const float* fc0_b  = (const float*)d_in[3];
    const float* Wx_rel = (const float*)d_in[4];
    const float* Wx_root= (const float*)d_in[5];
    const float* bx     = (const float*)d_in[6];
    // d_in[7] Wh_rel, d_in[8] Wh_root multiply zeros -> unused
    const float* bh     = (const float*)d_in[9];
    const float* fc_w   = (const float*)d_in[10];
    const float* fc_b   = (const float*)d_in[11];
    float* out = (float*)d_out;

    int n_real = in_sizes[0] / FIN;     // 2500
    int E = in_sizes[1] / 2;            // 300000
    if (E > EMAX) E = EMAX;

    // output is the flattened tuple (out[n_real], H[3000,128]) when sized for it
    int write_H = (out_size >= n_real + NPAD * OUTD) ? 1 : 0;
    float* Hout = out + n_real;

    // CSR build
    init_kernel<<<(NPAD + 255) / 256, 256>>>();
    hist_kernel<<<(E + 255) / 256, 256>>>(ei, E);
    scan_kernel<<<1, 1024>>>();
    scatter_kernel<<<(E + 255) / 256, 256>>>(ei, E);

    // xh = relu(x @ fc0_w^T + b): split-K GEMM + epilogue; padded rows constant
    gemm1_kernel<<<dim3((n_real + BM - 1) / BM, H1DIM / BN, SPLITK), 128>>>(x, fc0_w, n_real);
    xh_epilogue_kernel<<<(n_real * (H1DIM / 4) + 255) / 256, 256>>>(fc0_b, n_real);
    if (NPAD > n_real)
        fill_xh_kernel<<<NPAD - n_real, H1DIM>>>(fc0_b, n_real);

    // segment mean (2 nodes per CTA, 8-deep gather batches)
    agg_kernel<<<(NPAD + 1) / 2, 128>>>();

    // gates
    gemm2_kernel<<<dim3((NPAD + BM - 1) / BM, (NGATE * OUTD) / BN), 128>>>(Wx_rel, Wx_root, bx, bh);

    // LSTM elementwise + linear head (2 nodes per CTA)
    lstm_out_kernel<<<(NPAD + 1) / 2, 256>>>(fc_w, fc_b, out, n_real, write_H, Hout);
}